// round 14
// baseline (speedup 1.0000x reference)
#include <cuda_runtime.h>
#include <math.h>

#define NN 100000
#define EE 1600000
#define EPAD (EE + NN)   // edges + max one pad slot per node
#define FIN 64
#define HH 32
#define NCH 196          // ceil(NN/512)

// ---------------- device scratch (static, allocation-free) ----------------
__device__ __align__(16) float g_xr[NN * HH];     // rel-transformed features for gather
__device__ __align__(16) float g_rt[NN * HH];     // root-transformed features (+bias)
__device__ __align__(16) float g_h1[NN * HH];     // relu(agg + rt) after gather1
__device__ __align__(16) float g_pvsrc[NN * 2];   // per-node (h2 . Wp_rel, h2 . Wv_rel)
__device__ __align__(16) float g_pvrt[NN * 2];    // per-node (h2 . Wp_root + bp, h2 . Wv_root + bv)
__device__ __align__(16) float g_pm[NN];
__device__ __align__(16) int2  g_edges[EPAD];     // dst-sorted (src, w-bits), even-aligned segments
__device__ int g_cnt[NN];
__device__ int g_off[NN];
__device__ int g_wpos[NN];
__device__ int g_bsum[NCH];
__device__ int g_mlist[NN];
__device__ int g_mcnt;
__device__ int g_done1;
__device__ int g_done2;

// ---------------- f32x2 helpers ----------------
__device__ __forceinline__ void lds2u64(unsigned long long& a, unsigned long long& b, const float* p) {
    unsigned addr = (unsigned)__cvta_generic_to_shared(p);
    asm volatile("ld.shared.v2.u64 {%0,%1}, [%2];" : "=l"(a), "=l"(b) : "r"(addr));
}
__device__ __forceinline__ void fma2(unsigned long long& d, unsigned long long a, unsigned long long b) {
    asm volatile("fma.rn.f32x2 %0, %1, %2, %0;" : "+l"(d) : "l"(a), "l"(b));
}
__device__ __forceinline__ unsigned long long pack2(float x) {
    unsigned xi = __float_as_uint(x);
    unsigned long long r;
    asm volatile("mov.b64 %0, {%1,%1};" : "=l"(r) : "r"(xi));
    return r;
}

// one 32-output matmul phase over a weight panel in smem
__device__ __forceinline__ void mm_phase64(const float4* __restrict__ xv, const float* __restrict__ W,
                                           unsigned long long* acc) {
#pragma unroll
    for (int k4 = 0; k4 < FIN / 4; k4++) {
        float4 xk = xv[k4];
        float xs[4] = {xk.x, xk.y, xk.z, xk.w};
#pragma unroll
        for (int kk = 0; kk < 4; kk++) {
            int k = k4 * 4 + kk;
            unsigned long long xx = pack2(xs[kk]);
#pragma unroll
            for (int j = 0; j < 8; j++) {
                unsigned long long w0, w1;
                lds2u64(w0, w1, W + k * HH + j * 4);
                fma2(acc[j * 2], xx, w0);
                fma2(acc[j * 2 + 1], xx, w1);
            }
        }
    }
}

__device__ __forceinline__ void mm_phase32(const float4* __restrict__ xv, const float* __restrict__ W,
                                           unsigned long long* acc) {
#pragma unroll
    for (int k4 = 0; k4 < HH / 4; k4++) {
        float4 xk = xv[k4];
        float xs[4] = {xk.x, xk.y, xk.z, xk.w};
#pragma unroll
        for (int kk = 0; kk < 4; kk++) {
            int k = k4 * 4 + kk;
            unsigned long long xx = pack2(xs[kk]);
#pragma unroll
            for (int j = 0; j < 8; j++) {
                unsigned long long w0, w1;
                lds2u64(w0, w1, W + k * HH + j * 4);
                fma2(acc[j * 2], xx, w0);
                fma2(acc[j * 2 + 1], xx, w1);
            }
        }
    }
}

// ---------------- fused: xr = x@Win_rel, rt = x@Win_root + bin (two phases); zero scratch/out ----------------
__global__ __launch_bounds__(256) void k_xw64f(const float* __restrict__ x,
                                               const float* __restrict__ Wrel,
                                               const float* __restrict__ Wroot,
                                               const float* __restrict__ b,
                                               float* __restrict__ out) {
    __shared__ __align__(16) float sWa[FIN * HH];
    __shared__ __align__(16) float sWb[FIN * HH];
    __shared__ __align__(16) float sb[HH];
    for (int i = threadIdx.x; i < FIN * HH; i += blockDim.x) {
        sWa[i] = Wrel[i];
        sWb[i] = Wroot[i];
    }
    if (threadIdx.x < HH) sb[threadIdx.x] = b[threadIdx.x];
    __syncthreads();
    int node = blockIdx.x * blockDim.x + threadIdx.x;
    if (node == 0) { g_mcnt = 0; g_done1 = 0; g_done2 = 0; }
    if (node >= NN) return;
    g_cnt[node] = 0;
    out[node] = 0.f;          // softmax default (unmasked -> 0)
    out[NN + node] = 0.f;     // masked value default
    const float4* xv = (const float4*)(x + (size_t)node * FIN);
    unsigned long long acc[HH / 2];
    // phase 1: rel
#pragma unroll
    for (int j = 0; j < HH / 2; j++) acc[j] = 0ULL;
    mm_phase64(xv, sWa, acc);
    ulonglong2* oa = (ulonglong2*)(g_xr + (size_t)node * HH);
#pragma unroll
    for (int j = 0; j < 8; j++) oa[j] = make_ulonglong2(acc[j * 2], acc[j * 2 + 1]);
    // phase 2: root + bias (x row re-read, L1-hot)
    const unsigned long long* sb64 = (const unsigned long long*)sb;
#pragma unroll
    for (int j = 0; j < HH / 2; j++) acc[j] = sb64[j];
    mm_phase64(xv, sWb, acc);
    ulonglong2* ob = (ulonglong2*)(g_rt + (size_t)node * HH);
#pragma unroll
    for (int j = 0; j < 8; j++) ob[j] = make_ulonglong2(acc[j * 2], acc[j * 2 + 1]);
}

// ---------------- histogram of destinations ----------------
__global__ void k_hist(const int* __restrict__ ei) {
    int e = blockIdx.x * blockDim.x + threadIdx.x;
    if (e >= EE) return;
    atomicAdd(&g_cnt[__ldg(ei + EE + e)], 1);
}

// ---------------- fused scan + scatter with even-padded segments ----------------
__global__ __launch_bounds__(512) void k_scan_scatter(const int* __restrict__ ei,
                                                      const float* __restrict__ ew) {
    __shared__ int sh[512];
    __shared__ int sred[512];
    int tid = threadIdx.x;
    int bid = blockIdx.x;
    int i = bid * 512 + tid;
    int v = (i < NN) ? g_cnt[i] : 0;
    int pv_ = (v + 1) & ~1;          // padded-to-even count
    sh[tid] = pv_;
    __syncthreads();
    // Hillis-Steele inclusive scan of padded counts
    for (int off = 1; off < 512; off <<= 1) {
        int t = (tid >= off) ? sh[tid - off] : 0;
        __syncthreads();
        sh[tid] += t;
        __syncthreads();
    }
    if (tid == 511) g_bsum[bid] = sh[511];
    // grid sync 1: all block sums published
    __threadfence();
    __syncthreads();
    if (tid == 0) {
        atomicAdd(&g_done1, 1);
        while (atomicAdd(&g_done1, 0) < NCH) { }
    }
    __syncthreads();
    __threadfence();
    // each block computes its own base = sum of g_bsum[0..bid-1]
    sred[tid] = (tid < bid) ? g_bsum[tid] : 0;
    __syncthreads();
#pragma unroll
    for (int s = 256; s; s >>= 1) {
        if (tid < s) sred[tid] += sred[tid + s];
        __syncthreads();
    }
    int base = sred[0];
    if (i < NN) {
        int excl = base + sh[tid] - pv_;     // even
        g_off[i] = excl;
        g_wpos[i] = excl;
        if (v & 1) g_edges[excl + v] = make_int2(-1, 0);   // zero-weight pad (src=-1 never matches cur)
    }
    // grid sync 2: all offsets written
    __threadfence();
    __syncthreads();
    if (tid == 0) {
        atomicAdd(&g_done2, 1);
        while (atomicAdd(&g_done2, 0) < NCH) { }
    }
    __syncthreads();
    __threadfence();
    // scatter, grid-stride over edges
    int gtid = bid * 512 + tid;
    for (int e = gtid; e < EE; e += NCH * 512) {
        int s = __ldg(ei + e);
        int d = __ldg(ei + EE + e);
        float w = __ldg(ew + e);
        int pos = atomicAdd(&g_wpos[d], 1);
        g_edges[pos] = make_int2(s, __float_as_int(w));
    }
}

// ---------------- gather1: 8 lanes/node, int4 dual-edge loads; h1 = relu(agg + rt); mask list ----------------
__global__ __launch_bounds__(256) void k_gather1(const int* __restrict__ curp) {
    int gt = blockIdx.x * blockDim.x + threadIdx.x;
    int node = gt >> 3;
    if (node >= NN) return;
    int sub = gt & 7;
    int beg = g_off[node];
    int cntp = (g_cnt[node] + 1) & ~1;
    int cur = __ldg(curp);
    const int4* ep4 = (const int4*)(g_edges + beg);
    float4 a0 = make_float4(0.f, 0.f, 0.f, 0.f);
    float4 a1 = make_float4(0.f, 0.f, 0.f, 0.f);
    int hit = 0;
    for (int t = 0; t < cntp; t += 2) {
        int4 ee = ep4[t >> 1];
        float w0 = __int_as_float(ee.y), w1 = __int_as_float(ee.w);
        int s0 = abs(ee.x), s1 = abs(ee.z);      // pad src=-1 -> row 1 with w=0 (no contribution)
        float4 r0 = ((const float4*)(g_xr + (size_t)s0 * HH))[sub];
        float4 r1 = ((const float4*)(g_xr + (size_t)s1 * HH))[sub];
        a0.x = fmaf(w0, r0.x, a0.x); a0.y = fmaf(w0, r0.y, a0.y);
        a0.z = fmaf(w0, r0.z, a0.z); a0.w = fmaf(w0, r0.w, a0.w);
        a1.x = fmaf(w1, r1.x, a1.x); a1.y = fmaf(w1, r1.y, a1.y);
        a1.z = fmaf(w1, r1.z, a1.z); a1.w = fmaf(w1, r1.w, a1.w);
        hit |= (ee.x == cur) | (ee.z == cur);
    }
    float4 rt = ((const float4*)(g_rt + (size_t)node * HH))[sub];
    float4 h;
    h.x = fmaxf(a0.x + a1.x + rt.x, 0.f);
    h.y = fmaxf(a0.y + a1.y + rt.y, 0.f);
    h.z = fmaxf(a0.z + a1.z + rt.z, 0.f);
    h.w = fmaxf(a0.w + a1.w + rt.w, 0.f);
    ((float4*)(g_h1 + (size_t)node * HH))[sub] = h;
    if (sub == 0 && hit) {
        int p = atomicAdd(&g_mcnt, 1);
        g_mlist[p] = node;
    }
}

// ---------------- node1: xr = h1@Wh_rel; rt = h1@Wh_root + bh (two phases) ----------------
__global__ __launch_bounds__(256) void k_node1(const float* __restrict__ Whrel,
                                               const float* __restrict__ Whroot,
                                               const float* __restrict__ bh) {
    __shared__ __align__(16) float sWa[HH * HH];
    __shared__ __align__(16) float sWb[HH * HH];
    __shared__ __align__(16) float sb[HH];
    for (int i = threadIdx.x; i < HH * HH; i += blockDim.x) {
        sWa[i] = Whrel[i];
        sWb[i] = Whroot[i];
    }
    if (threadIdx.x < HH) sb[threadIdx.x] = bh[threadIdx.x];
    __syncthreads();
    int node = blockIdx.x * blockDim.x + threadIdx.x;
    if (node >= NN) return;
    const float4* hv = (const float4*)(g_h1 + (size_t)node * HH);
    unsigned long long acc[HH / 2];
#pragma unroll
    for (int j = 0; j < HH / 2; j++) acc[j] = 0ULL;
    mm_phase32(hv, sWa, acc);
    ulonglong2* oa = (ulonglong2*)(g_xr + (size_t)node * HH);
#pragma unroll
    for (int j = 0; j < 8; j++) oa[j] = make_ulonglong2(acc[j * 2], acc[j * 2 + 1]);
    const unsigned long long* sb64 = (const unsigned long long*)sb;
#pragma unroll
    for (int j = 0; j < HH / 2; j++) acc[j] = sb64[j];
    mm_phase32(hv, sWb, acc);
    ulonglong2* ob = (ulonglong2*)(g_rt + (size_t)node * HH);
#pragma unroll
    for (int j = 0; j < 8; j++) ob[j] = make_ulonglong2(acc[j * 2], acc[j * 2 + 1]);
}

// ---------------- gather2: int4 dual-edge loads; agg + relu + 4 scalar heads fused ----------------
__global__ __launch_bounds__(256) void k_gather2(const float* __restrict__ Wprel,
                                                 const float* __restrict__ Wvrel,
                                                 const float* __restrict__ Wproot,
                                                 const float* __restrict__ Wvroot,
                                                 const float* __restrict__ bp,
                                                 const float* __restrict__ bv) {
    int gt = blockIdx.x * blockDim.x + threadIdx.x;
    int node = gt >> 3;
    if (node >= NN) return;
    int sub = gt & 7;
    int beg = g_off[node];
    int cntp = (g_cnt[node] + 1) & ~1;
    const int4* ep4 = (const int4*)(g_edges + beg);
    float4 a0 = make_float4(0.f, 0.f, 0.f, 0.f);
    float4 a1 = make_float4(0.f, 0.f, 0.f, 0.f);
    for (int t = 0; t < cntp; t += 2) {
        int4 ee = ep4[t >> 1];
        float w0 = __int_as_float(ee.y), w1 = __int_as_float(ee.w);
        int s0 = abs(ee.x), s1 = abs(ee.z);
        float4 r0 = ((const float4*)(g_xr + (size_t)s0 * HH))[sub];
        float4 r1 = ((const float4*)(g_xr + (size_t)s1 * HH))[sub];
        a0.x = fmaf(w0, r0.x, a0.x); a0.y = fmaf(w0, r0.y, a0.y);
        a0.z = fmaf(w0, r0.z, a0.z); a0.w = fmaf(w0, r0.w, a0.w);
        a1.x = fmaf(w1, r1.x, a1.x); a1.y = fmaf(w1, r1.y, a1.y);
        a1.z = fmaf(w1, r1.z, a1.z); a1.w = fmaf(w1, r1.w, a1.w);
    }
    float4 rt = ((const float4*)(g_rt + (size_t)node * HH))[sub];
    float h0 = fmaxf(a0.x + a1.x + rt.x, 0.f);
    float h1 = fmaxf(a0.y + a1.y + rt.y, 0.f);
    float h2 = fmaxf(a0.z + a1.z + rt.z, 0.f);
    float h3 = fmaxf(a0.w + a1.w + rt.w, 0.f);
    float4 wpr = __ldg((const float4*)Wprel + sub);
    float4 wvr = __ldg((const float4*)Wvrel + sub);
    float4 wpo = __ldg((const float4*)Wproot + sub);
    float4 wvo = __ldg((const float4*)Wvroot + sub);
    float pr = h0 * wpr.x + h1 * wpr.y + h2 * wpr.z + h3 * wpr.w;
    float vr = h0 * wvr.x + h1 * wvr.y + h2 * wvr.z + h3 * wvr.w;
    float po = h0 * wpo.x + h1 * wpo.y + h2 * wpo.z + h3 * wpo.w;
    float vo = h0 * wvo.x + h1 * wvo.y + h2 * wvo.z + h3 * wvo.w;
#pragma unroll
    for (int o = 4; o; o >>= 1) {
        pr += __shfl_xor_sync(0xFFFFFFFFu, pr, o);
        vr += __shfl_xor_sync(0xFFFFFFFFu, vr, o);
        po += __shfl_xor_sync(0xFFFFFFFFu, po, o);
        vo += __shfl_xor_sync(0xFFFFFFFFu, vo, o);
    }
    if (sub == 0) {
        *(float2*)(g_pvsrc + (size_t)node * 2) = make_float2(pr, vr);
        *(float2*)(g_pvrt + (size_t)node * 2) = make_float2(po + __ldg(bp), vo + __ldg(bv));
    }
}

// ---------------- masked-node pv gather + softmax, single block ----------------
__global__ __launch_bounds__(1024) void k_gpv_final(float* __restrict__ out) {
    __shared__ float red[32];
    __shared__ float s_max, s_sum;
    int tid = threadIdx.x;
    int wid = tid >> 5, lane = tid & 31;
    int mcnt = g_mcnt;
    for (int m = wid; m < mcnt; m += 32) {
        int node = g_mlist[m];
        int beg = g_off[node];
        int cnt = g_cnt[node];          // TRUE count: pad slot excluded
        float ap = 0.f, av = 0.f;
        for (int i = lane; i < cnt; i += 32) {
            int2 e = g_edges[beg + i];
            float w = __int_as_float(e.y);
            float2 pv = *(const float2*)(g_pvsrc + (size_t)e.x * 2);
            ap += w * pv.x;
            av += w * pv.y;
        }
#pragma unroll
        for (int o = 16; o; o >>= 1) {
            ap += __shfl_xor_sync(0xFFFFFFFFu, ap, o);
            av += __shfl_xor_sync(0xFFFFFFFFu, av, o);
        }
        if (lane == 0) {
            float2 rt = *(const float2*)(g_pvrt + (size_t)node * 2);
            float p = ap + rt.x;
            float v = av + rt.y;
            float pm = (p == 0.f) ? __int_as_float(0xFF800000) : p;
            g_pm[node] = pm;
            out[NN + node] = v;
        }
    }
    __syncthreads();
    float mx = __int_as_float(0xFF800000);
    for (int m = tid; m < mcnt; m += 1024) mx = fmaxf(mx, g_pm[g_mlist[m]]);
#pragma unroll
    for (int o = 16; o; o >>= 1) mx = fmaxf(mx, __shfl_xor_sync(0xFFFFFFFFu, mx, o));
    if (lane == 0) red[wid] = mx;
    __syncthreads();
    if (tid < 32) {
        float v = red[tid];
#pragma unroll
        for (int o = 16; o; o >>= 1) v = fmaxf(v, __shfl_xor_sync(0xFFFFFFFFu, v, o));
        if (tid == 0) s_max = v;
    }
    __syncthreads();
    float maxv = s_max;
    float sm = 0.f;
    for (int m = tid; m < mcnt; m += 1024) {
        int node = g_mlist[m];
        float e = expf(g_pm[node] - maxv);
        g_pm[node] = e;
        sm += e;
    }
#pragma unroll
    for (int o = 16; o; o >>= 1) sm += __shfl_xor_sync(0xFFFFFFFFu, sm, o);
    if (lane == 0) red[wid] = sm;
    __syncthreads();
    if (tid < 32) {
        float v = red[tid];
#pragma unroll
        for (int o = 16; o; o >>= 1) v += __shfl_xor_sync(0xFFFFFFFFu, v, o);
        if (tid == 0) s_sum = v;
    }
    __syncthreads();
    float inv = 1.f / s_sum;
    for (int m = tid; m < mcnt; m += 1024) {
        int node = g_mlist[m];
        out[node] = g_pm[node] * inv;
    }
}

// ---------------- launch ----------------
extern "C" void kernel_launch(void* const* d_in, const int* in_sizes, int n_in,
                              void* d_out, int out_size) {
    const float* x        = (const float*)d_in[0];
    const int*   ei       = (const int*)d_in[1];
    const float* ew       = (const float*)d_in[2];
    const int*   cur      = (const int*)d_in[3];
    const float* Win_rel  = (const float*)d_in[4];
    const float* bin_rel  = (const float*)d_in[5];
    const float* Win_root = (const float*)d_in[6];
    const float* Wh_rel   = (const float*)d_in[7];
    const float* bh_rel   = (const float*)d_in[8];
    const float* Wh_root  = (const float*)d_in[9];
    const float* Wp_rel   = (const float*)d_in[10];
    const float* bp_rel   = (const float*)d_in[11];
    const float* Wp_root  = (const float*)d_in[12];
    const float* Wv_rel   = (const float*)d_in[13];
    const float* bv_rel   = (const float*)d_in[14];
    const float* Wv_root  = (const float*)d_in[15];
    float* out = (float*)d_out;

    const int TB = 256;
    const int gn = (NN + TB - 1) / TB;
    const int ge = (EE + TB - 1) / TB;
    const int gg = (NN * 8 + TB - 1) / TB;   // 8 lanes per node (gathers)

    k_xw64f<<<gn, TB>>>(x, Win_rel, Win_root, bin_rel, out);          // 0
    k_hist<<<ge, TB>>>(ei);                                            // 1
    k_scan_scatter<<<NCH, 512>>>(ei, ew);                              // 2
    k_gather1<<<gg, TB>>>(cur);                                        // 3
    k_node1<<<gn, TB>>>(Wh_rel, Wh_root, bh_rel);                      // 4
    k_gather2<<<gg, TB>>>(Wp_rel, Wv_rel, Wp_root, Wv_root, bp_rel, bv_rel);  // 5 <- ncu capture
    k_gpv_final<<<1, 1024>>>(out);                                     // 6
}

// round 15
// speedup vs baseline: 1.3112x; 1.3112x over previous
#include <cuda_runtime.h>
#include <math.h>

#define NN 100000
#define EE 1600000
#define FIN 64
#define HH 32
#define NCH 196          // ceil(NN/512)

// ---------------- device scratch (static, allocation-free) ----------------
__device__ __align__(16) float g_xr[NN * HH];     // rel-transformed features
__device__ __align__(16) float g_rt[NN * HH];     // root-transformed features (+bias)
__device__ __align__(16) float g_h1[NN * HH];     // relu(agg + rt) for S1 nodes
__device__ __align__(16) float g_pvsrc[NN * 2];
__device__ __align__(16) float g_pvrt[NN * 2];
__device__ __align__(16) float g_pm[NN];
__device__ __align__(16) int2  g_edges[EE];       // dst-sorted (src, w-bits)
__device__ int g_cnt[NN];
__device__ int g_off[NN];
__device__ int g_wpos[NN];
__device__ int g_bsum[NCH];
__device__ int g_mlist[NN];    // masked nodes
__device__ int g_s0list[NN];   // frontier 0 (h2 needed)
__device__ int g_s1list[NN];   // frontier 1 (h1 needed)
__device__ int g_bm[NN];       // bitmaps
__device__ int g_b0[NN];
__device__ int g_b1[NN];
__device__ int g_mcnt, g_s0cnt, g_s1cnt;
__device__ int g_done1, g_done2;

// ---------------- f32x2 helpers ----------------
__device__ __forceinline__ void lds2u64(unsigned long long& a, unsigned long long& b, const float* p) {
    unsigned addr = (unsigned)__cvta_generic_to_shared(p);
    asm volatile("ld.shared.v2.u64 {%0,%1}, [%2];" : "=l"(a), "=l"(b) : "r"(addr));
}
__device__ __forceinline__ void fma2(unsigned long long& d, unsigned long long a, unsigned long long b) {
    asm volatile("fma.rn.f32x2 %0, %1, %2, %0;" : "+l"(d) : "l"(a), "l"(b));
}
__device__ __forceinline__ unsigned long long pack2(float x) {
    unsigned xi = __float_as_uint(x);
    unsigned long long r;
    asm volatile("mov.b64 %0, {%1,%1};" : "=l"(r) : "r"(xi));
    return r;
}

__device__ __forceinline__ void mm_phase64(const float4* __restrict__ xv, const float* __restrict__ W,
                                           unsigned long long* acc) {
#pragma unroll
    for (int k4 = 0; k4 < FIN / 4; k4++) {
        float4 xk = xv[k4];
        float xs[4] = {xk.x, xk.y, xk.z, xk.w};
#pragma unroll
        for (int kk = 0; kk < 4; kk++) {
            int k = k4 * 4 + kk;
            unsigned long long xx = pack2(xs[kk]);
#pragma unroll
            for (int j = 0; j < 8; j++) {
                unsigned long long w0, w1;
                lds2u64(w0, w1, W + k * HH + j * 4);
                fma2(acc[j * 2], xx, w0);
                fma2(acc[j * 2 + 1], xx, w1);
            }
        }
    }
}

__device__ __forceinline__ void mm_phase32(const float4* __restrict__ xv, const float* __restrict__ W,
                                           unsigned long long* acc) {
#pragma unroll
    for (int k4 = 0; k4 < HH / 4; k4++) {
        float4 xk = xv[k4];
        float xs[4] = {xk.x, xk.y, xk.z, xk.w};
#pragma unroll
        for (int kk = 0; kk < 4; kk++) {
            int k = k4 * 4 + kk;
            unsigned long long xx = pack2(xs[kk]);
#pragma unroll
            for (int j = 0; j < 8; j++) {
                unsigned long long w0, w1;
                lds2u64(w0, w1, W + k * HH + j * 4);
                fma2(acc[j * 2], xx, w0);
                fma2(acc[j * 2 + 1], xx, w1);
            }
        }
    }
}

// ---------------- full feature transform + zero scratch/out/bitmaps ----------------
__global__ __launch_bounds__(256) void k_xw64f(const float* __restrict__ x,
                                               const float* __restrict__ Wrel,
                                               const float* __restrict__ Wroot,
                                               const float* __restrict__ b,
                                               float* __restrict__ out) {
    __shared__ __align__(16) float sWa[FIN * HH];
    __shared__ __align__(16) float sWb[FIN * HH];
    __shared__ __align__(16) float sb[HH];
    for (int i = threadIdx.x; i < FIN * HH; i += blockDim.x) {
        sWa[i] = Wrel[i];
        sWb[i] = Wroot[i];
    }
    if (threadIdx.x < HH) sb[threadIdx.x] = b[threadIdx.x];
    __syncthreads();
    int node = blockIdx.x * blockDim.x + threadIdx.x;
    if (node == 0) { g_mcnt = 0; g_s0cnt = 0; g_s1cnt = 0; g_done1 = 0; g_done2 = 0; }
    if (node >= NN) return;
    g_cnt[node] = 0;
    g_bm[node] = 0;
    g_b0[node] = 0;
    g_b1[node] = 0;
    out[node] = 0.f;
    out[NN + node] = 0.f;
    const float4* xv = (const float4*)(x + (size_t)node * FIN);
    unsigned long long acc[HH / 2];
#pragma unroll
    for (int j = 0; j < HH / 2; j++) acc[j] = 0ULL;
    mm_phase64(xv, sWa, acc);
    ulonglong2* oa = (ulonglong2*)(g_xr + (size_t)node * HH);
#pragma unroll
    for (int j = 0; j < 8; j++) oa[j] = make_ulonglong2(acc[j * 2], acc[j * 2 + 1]);
    const unsigned long long* sb64 = (const unsigned long long*)sb;
#pragma unroll
    for (int j = 0; j < HH / 2; j++) acc[j] = sb64[j];
    mm_phase64(xv, sWb, acc);
    ulonglong2* ob = (ulonglong2*)(g_rt + (size_t)node * HH);
#pragma unroll
    for (int j = 0; j < 8; j++) ob[j] = make_ulonglong2(acc[j * 2], acc[j * 2 + 1]);
}

// ---------------- histogram + masked-node detection ----------------
__global__ void k_hist(const int* __restrict__ ei, const int* __restrict__ curp) {
    int e = blockIdx.x * blockDim.x + threadIdx.x;
    if (e >= EE) return;
    int s = __ldg(ei + e);
    int d = __ldg(ei + EE + e);
    atomicAdd(&g_cnt[d], 1);
    if (s == __ldg(curp)) {
        if (atomicExch(&g_bm[d], 1) == 0) {
            int p = atomicAdd(&g_mcnt, 1);
            g_mlist[p] = d;
        }
    }
}

// ---------------- fused scan + scatter (R6-proven) ----------------
__global__ __launch_bounds__(512) void k_scan_scatter(const int* __restrict__ ei,
                                                      const float* __restrict__ ew) {
    __shared__ int sh[512];
    __shared__ int sred[512];
    int tid = threadIdx.x;
    int bid = blockIdx.x;
    int i = bid * 512 + tid;
    int v = (i < NN) ? g_cnt[i] : 0;
    sh[tid] = v;
    __syncthreads();
    for (int off = 1; off < 512; off <<= 1) {
        int t = (tid >= off) ? sh[tid - off] : 0;
        __syncthreads();
        sh[tid] += t;
        __syncthreads();
    }
    if (tid == 511) g_bsum[bid] = sh[511];
    __threadfence();
    __syncthreads();
    if (tid == 0) {
        atomicAdd(&g_done1, 1);
        while (atomicAdd(&g_done1, 0) < NCH) { }
    }
    __syncthreads();
    __threadfence();
    sred[tid] = (tid < bid) ? g_bsum[tid] : 0;
    __syncthreads();
#pragma unroll
    for (int s = 256; s; s >>= 1) {
        if (tid < s) sred[tid] += sred[tid + s];
        __syncthreads();
    }
    int base = sred[0];
    if (i < NN) {
        int excl = base + sh[tid] - v;
        g_off[i] = excl;
        g_wpos[i] = excl;
    }
    __threadfence();
    __syncthreads();
    if (tid == 0) {
        atomicAdd(&g_done2, 1);
        while (atomicAdd(&g_done2, 0) < NCH) { }
    }
    __syncthreads();
    __threadfence();
    int gtid = bid * 512 + tid;
    for (int e = gtid; e < EE; e += NCH * 512) {
        int s = __ldg(ei + e);
        int d = __ldg(ei + EE + e);
        float w = __ldg(ew + e);
        int pos = atomicAdd(&g_wpos[d], 1);
        g_edges[pos] = make_int2(s, __float_as_int(w));
    }
}

// ---------------- frontier helpers ----------------
__device__ __forceinline__ void add_set(int n, int* bitmap, int* list, int* cntp) {
    if (atomicExch(&bitmap[n], 1) == 0) {
        int p = atomicAdd(cntp, 1);
        list[p] = n;
    }
}

// S0 = masked ∪ srcs(in-edges(masked))
__global__ void k_expand0() {
    int gt = blockIdx.x * blockDim.x + threadIdx.x;
    int lane = gt & 31;
    int warp = gt >> 5;
    int nw = (gridDim.x * blockDim.x) >> 5;
    int cnt0 = g_mcnt;
    for (int m = warp; m < cnt0; m += nw) {
        int node = g_mlist[m];
        if (lane == 0) add_set(node, g_b0, g_s0list, &g_s0cnt);
        int beg = g_off[node];
        int c = g_cnt[node];
        for (int i = lane; i < c; i += 32)
            add_set(g_edges[beg + i].x, g_b0, g_s0list, &g_s0cnt);
    }
}

// S1 = S0 ∪ srcs(in-edges(S0))
__global__ void k_expand1() {
    int gt = blockIdx.x * blockDim.x + threadIdx.x;
    int lane = gt & 31;
    int warp = gt >> 5;
    int nw = (gridDim.x * blockDim.x) >> 5;
    int cnt0 = g_s0cnt;
    for (int m = warp; m < cnt0; m += nw) {
        int node = g_s0list[m];
        if (lane == 0) add_set(node, g_b1, g_s1list, &g_s1cnt);
        int beg = g_off[node];
        int c = g_cnt[node];
        for (int i = lane; i < c; i += 32)
            add_set(g_edges[beg + i].x, g_b1, g_s1list, &g_s1cnt);
    }
}

// ---------------- gather1 over S1: h1 = relu(agg(xr) + rt), 8 lanes/node, unroll 2 ----------------
__global__ __launch_bounds__(256) void k_gather1_sel() {
    int gt = blockIdx.x * blockDim.x + threadIdx.x;
    int widx = gt >> 3;
    int sub = gt & 7;
    int stride = (gridDim.x * blockDim.x) >> 3;
    int s1cnt = g_s1cnt;
    for (int m = widx; m < s1cnt; m += stride) {
        int node = g_s1list[m];
        int beg = g_off[node];
        int cnt = g_cnt[node];
        const int2* ep = g_edges + beg;
        float4 a0 = make_float4(0.f, 0.f, 0.f, 0.f);
        float4 a1 = make_float4(0.f, 0.f, 0.f, 0.f);
        int t = 0;
        for (; t + 2 <= cnt; t += 2) {
            int2 e0 = ep[t], e1 = ep[t + 1];
            float w0 = __int_as_float(e0.y), w1 = __int_as_float(e1.y);
            float4 r0 = ((const float4*)(g_xr + (size_t)e0.x * HH))[sub];
            float4 r1 = ((const float4*)(g_xr + (size_t)e1.x * HH))[sub];
            a0.x = fmaf(w0, r0.x, a0.x); a0.y = fmaf(w0, r0.y, a0.y);
            a0.z = fmaf(w0, r0.z, a0.z); a0.w = fmaf(w0, r0.w, a0.w);
            a1.x = fmaf(w1, r1.x, a1.x); a1.y = fmaf(w1, r1.y, a1.y);
            a1.z = fmaf(w1, r1.z, a1.z); a1.w = fmaf(w1, r1.w, a1.w);
        }
        if (t < cnt) {
            int2 e0 = ep[t];
            float w0 = __int_as_float(e0.y);
            float4 r0 = ((const float4*)(g_xr + (size_t)e0.x * HH))[sub];
            a0.x = fmaf(w0, r0.x, a0.x); a0.y = fmaf(w0, r0.y, a0.y);
            a0.z = fmaf(w0, r0.z, a0.z); a0.w = fmaf(w0, r0.w, a0.w);
        }
        float4 rt = ((const float4*)(g_rt + (size_t)node * HH))[sub];
        float4 h;
        h.x = fmaxf(a0.x + a1.x + rt.x, 0.f);
        h.y = fmaxf(a0.y + a1.y + rt.y, 0.f);
        h.z = fmaxf(a0.z + a1.z + rt.z, 0.f);
        h.w = fmaxf(a0.w + a1.w + rt.w, 0.f);
        ((float4*)(g_h1 + (size_t)node * HH))[sub] = h;
    }
}

// ---------------- node1 over S1: xr = h1@Wh_rel; rt = h1@Wh_root + bh ----------------
__global__ __launch_bounds__(256) void k_node1_sel(const float* __restrict__ Whrel,
                                                   const float* __restrict__ Whroot,
                                                   const float* __restrict__ bh) {
    __shared__ __align__(16) float sWa[HH * HH];
    __shared__ __align__(16) float sWb[HH * HH];
    __shared__ __align__(16) float sb[HH];
    for (int i = threadIdx.x; i < HH * HH; i += blockDim.x) {
        sWa[i] = Whrel[i];
        sWb[i] = Whroot[i];
    }
    if (threadIdx.x < HH) sb[threadIdx.x] = bh[threadIdx.x];
    __syncthreads();
    int gt = blockIdx.x * blockDim.x + threadIdx.x;
    int stride = gridDim.x * blockDim.x;
    int s1cnt = g_s1cnt;
    for (int m = gt; m < s1cnt; m += stride) {
        int node = g_s1list[m];
        const float4* hv = (const float4*)(g_h1 + (size_t)node * HH);
        unsigned long long acc[HH / 2];
#pragma unroll
        for (int j = 0; j < HH / 2; j++) acc[j] = 0ULL;
        mm_phase32(hv, sWa, acc);
        ulonglong2* oa = (ulonglong2*)(g_xr + (size_t)node * HH);
#pragma unroll
        for (int j = 0; j < 8; j++) oa[j] = make_ulonglong2(acc[j * 2], acc[j * 2 + 1]);
        const unsigned long long* sb64 = (const unsigned long long*)sb;
#pragma unroll
        for (int j = 0; j < HH / 2; j++) acc[j] = sb64[j];
        mm_phase32(hv, sWb, acc);
        ulonglong2* ob = (ulonglong2*)(g_rt + (size_t)node * HH);
#pragma unroll
        for (int j = 0; j < 8; j++) ob[j] = make_ulonglong2(acc[j * 2], acc[j * 2 + 1]);
    }
}

// ---------------- gather2 over S0: h2 heads -> pvsrc/pvrt ----------------
__global__ __launch_bounds__(256) void k_gather2_sel(const float* __restrict__ Wprel,
                                                     const float* __restrict__ Wvrel,
                                                     const float* __restrict__ Wproot,
                                                     const float* __restrict__ Wvroot,
                                                     const float* __restrict__ bp,
                                                     const float* __restrict__ bv) {
    int gt = blockIdx.x * blockDim.x + threadIdx.x;
    int widx = gt >> 3;
    int sub = gt & 7;
    int stride = (gridDim.x * blockDim.x) >> 3;
    int s0cnt = g_s0cnt;
    float4 wpr = __ldg((const float4*)Wprel + sub);
    float4 wvr = __ldg((const float4*)Wvrel + sub);
    float4 wpo = __ldg((const float4*)Wproot + sub);
    float4 wvo = __ldg((const float4*)Wvroot + sub);
    for (int m = widx; m < s0cnt; m += stride) {
        int node = g_s0list[m];
        int beg = g_off[node];
        int cnt = g_cnt[node];
        const int2* ep = g_edges + beg;
        float4 a0 = make_float4(0.f, 0.f, 0.f, 0.f);
        float4 a1 = make_float4(0.f, 0.f, 0.f, 0.f);
        int t = 0;
        for (; t + 2 <= cnt; t += 2) {
            int2 e0 = ep[t], e1 = ep[t + 1];
            float w0 = __int_as_float(e0.y), w1 = __int_as_float(e1.y);
            float4 r0 = ((const float4*)(g_xr + (size_t)e0.x * HH))[sub];
            float4 r1 = ((const float4*)(g_xr + (size_t)e1.x * HH))[sub];
            a0.x = fmaf(w0, r0.x, a0.x); a0.y = fmaf(w0, r0.y, a0.y);
            a0.z = fmaf(w0, r0.z, a0.z); a0.w = fmaf(w0, r0.w, a0.w);
            a1.x = fmaf(w1, r1.x, a1.x); a1.y = fmaf(w1, r1.y, a1.y);
            a1.z = fmaf(w1, r1.z, a1.z); a1.w = fmaf(w1, r1.w, a1.w);
        }
        if (t < cnt) {
            int2 e0 = ep[t];
            float w0 = __int_as_float(e0.y);
            float4 r0 = ((const float4*)(g_xr + (size_t)e0.x * HH))[sub];
            a0.x = fmaf(w0, r0.x, a0.x); a0.y = fmaf(w0, r0.y, a0.y);
            a0.z = fmaf(w0, r0.z, a0.z); a0.w = fmaf(w0, r0.w, a0.w);
        }
        float4 rt = ((const float4*)(g_rt + (size_t)node * HH))[sub];
        float h0 = fmaxf(a0.x + a1.x + rt.x, 0.f);
        float h1 = fmaxf(a0.y + a1.y + rt.y, 0.f);
        float h2 = fmaxf(a0.z + a1.z + rt.z, 0.f);
        float h3 = fmaxf(a0.w + a1.w + rt.w, 0.f);
        float pr = h0 * wpr.x + h1 * wpr.y + h2 * wpr.z + h3 * wpr.w;
        float vr = h0 * wvr.x + h1 * wvr.y + h2 * wvr.z + h3 * wvr.w;
        float po = h0 * wpo.x + h1 * wpo.y + h2 * wpo.z + h3 * wpo.w;
        float vo = h0 * wvo.x + h1 * wvo.y + h2 * wvo.z + h3 * wvo.w;
#pragma unroll
        for (int o = 4; o; o >>= 1) {
            pr += __shfl_xor_sync(0xFFFFFFFFu, pr, o);
            vr += __shfl_xor_sync(0xFFFFFFFFu, vr, o);
            po += __shfl_xor_sync(0xFFFFFFFFu, po, o);
            vo += __shfl_xor_sync(0xFFFFFFFFu, vo, o);
        }
        if (sub == 0) {
            *(float2*)(g_pvsrc + (size_t)node * 2) = make_float2(pr, vr);
            *(float2*)(g_pvrt + (size_t)node * 2) = make_float2(po + __ldg(bp), vo + __ldg(bv));
        }
    }
}

// ---------------- masked-node pv gather + softmax, single block ----------------
__global__ __launch_bounds__(1024) void k_gpv_final(float* __restrict__ out) {
    __shared__ float red[32];
    __shared__ float s_max, s_sum;
    int tid = threadIdx.x;
    int wid = tid >> 5, lane = tid & 31;
    int mcnt = g_mcnt;
    for (int m = wid; m < mcnt; m += 32) {
        int node = g_mlist[m];
        int beg = g_off[node];
        int cnt = g_cnt[node];
        float ap = 0.f, av = 0.f;
        for (int i = lane; i < cnt; i += 32) {
            int2 e = g_edges[beg + i];
            float w = __int_as_float(e.y);
            float2 pv = *(const float2*)(g_pvsrc + (size_t)e.x * 2);
            ap += w * pv.x;
            av += w * pv.y;
        }
#pragma unroll
        for (int o = 16; o; o >>= 1) {
            ap += __shfl_xor_sync(0xFFFFFFFFu, ap, o);
            av += __shfl_xor_sync(0xFFFFFFFFu, av, o);
        }
        if (lane == 0) {
            float2 rt = *(const float2*)(g_pvrt + (size_t)node * 2);
            float p = ap + rt.x;
            float v = av + rt.y;
            float pm = (p == 0.f) ? __int_as_float(0xFF800000) : p;
            g_pm[node] = pm;
            out[NN + node] = v;
        }
    }
    __syncthreads();
    float mx = __int_as_float(0xFF800000);
    for (int m = tid; m < mcnt; m += 1024) mx = fmaxf(mx, g_pm[g_mlist[m]]);
#pragma unroll
    for (int o = 16; o; o >>= 1) mx = fmaxf(mx, __shfl_xor_sync(0xFFFFFFFFu, mx, o));
    if (lane == 0) red[wid] = mx;
    __syncthreads();
    if (tid < 32) {
        float v = red[tid];
#pragma unroll
        for (int o = 16; o; o >>= 1) v = fmaxf(v, __shfl_xor_sync(0xFFFFFFFFu, v, o));
        if (tid == 0) s_max = v;
    }
    __syncthreads();
    float maxv = s_max;
    float sm = 0.f;
    for (int m = tid; m < mcnt; m += 1024) {
        int node = g_mlist[m];
        float e = expf(g_pm[node] - maxv);
        g_pm[node] = e;
        sm += e;
    }
#pragma unroll
    for (int o = 16; o; o >>= 1) sm += __shfl_xor_sync(0xFFFFFFFFu, sm, o);
    if (lane == 0) red[wid] = sm;
    __syncthreads();
    if (tid < 32) {
        float v = red[tid];
#pragma unroll
        for (int o = 16; o; o >>= 1) v += __shfl_xor_sync(0xFFFFFFFFu, v, o);
        if (tid == 0) s_sum = v;
    }
    __syncthreads();
    float inv = 1.f / s_sum;
    for (int m = tid; m < mcnt; m += 1024) {
        int node = g_mlist[m];
        out[node] = g_pm[node] * inv;
    }
}

// ---------------- launch ----------------
extern "C" void kernel_launch(void* const* d_in, const int* in_sizes, int n_in,
                              void* d_out, int out_size) {
    const float* x        = (const float*)d_in[0];
    const int*   ei       = (const int*)d_in[1];
    const float* ew       = (const float*)d_in[2];
    const int*   cur      = (const int*)d_in[3];
    const float* Win_rel  = (const float*)d_in[4];
    const float* bin_rel  = (const float*)d_in[5];
    const float* Win_root = (const float*)d_in[6];
    const float* Wh_rel   = (const float*)d_in[7];
    const float* bh_rel   = (const float*)d_in[8];
    const float* Wh_root  = (const float*)d_in[9];
    const float* Wp_rel   = (const float*)d_in[10];
    const float* bp_rel   = (const float*)d_in[11];
    const float* Wp_root  = (const float*)d_in[12];
    const float* Wv_rel   = (const float*)d_in[13];
    const float* bv_rel   = (const float*)d_in[14];
    const float* Wv_root  = (const float*)d_in[15];
    float* out = (float*)d_out;

    const int TB = 256;
    const int gn = (NN + TB - 1) / TB;
    const int ge = (EE + TB - 1) / TB;

    k_xw64f<<<gn, TB>>>(x, Win_rel, Win_root, bin_rel, out);          // 0
    k_hist<<<ge, TB>>>(ei, cur);                                       // 1
    k_scan_scatter<<<NCH, 512>>>(ei, ew);                              // 2
    k_expand0<<<148, TB>>>();                                          // 3
    k_expand1<<<296, TB>>>();                                          // 4
    k_gather1_sel<<<1184, TB>>>();                                     // 5 <- ncu capture
    k_node1_sel<<<296, TB>>>(Wh_rel, Wh_root, bh_rel);                 // 6
    k_gather2_sel<<<64, TB>>>(Wp_rel, Wv_rel, Wp_root, Wv_root, bp_rel, bv_rel);  // 7
    k_gpv_final<<<1, 1024>>>(out);                                     // 8
}